// round 1
// baseline (speedup 1.0000x reference)
#include <cuda_runtime.h>
#include <cuda_fp16.h>

// CapsuleLayer dynamic routing, B200/sm_100a.
// Shapes: B=256 batch, I=16 in_units, C=1152 capsules, U=10 out units, S=32 unit size.
//
// Strategy:
//   K_init  : b_ij = 0, c_ij = 0.1 (softmax of zeros)
//   K_uhat  : UH[c][j][b] = sum_i W[c,u,s,i] * x[b,i,c]   (fp16 store, f32x2 FMA)
//   per routing iteration:
//     K_spass  : s_part[p][j][b] = sum_{c in slice p} c_ij[c,u] * UH[c][j][b]
//     K_squash : v = squash(sum_p s_part) ; writes v (fp16 for agreement) + d_out (fp32)
//     K_apass  : A[c,u] = sum_{b,s} UH*v ; b_ij += A/B ; softmax over u -> c_ij
//   (final iteration skips K_apass — reference discards the last b_ij update)

#define BB   256
#define IU   16
#define CC   1152
#define NU   10
#define SS   32
#define JJ   (NU*SS)      // 320
#define KX   (IU*CC)      // 18432
#define WSZ  (NU*SS*IU)   // 5120
#define CSPLIT 4
#define CCHUNK (CC/CSPLIT) // 288

// ---- device scratch (static: no runtime allocation allowed) ----
__device__ __half d_UH[(size_t)CC * JJ * BB];   // 188.7 MB, [c][j][b]
__device__ float  d_spart[CSPLIT][JJ * BB];     // partial s sums
__device__ __half d_vh[JJ * BB];                // v in fp16, [j][b] (fits L1)
__device__ float  d_bij[CC * NU];               // routing logits [c][u]
__device__ float  d_cij[NU * CC];               // softmax coeffs, transposed [u][c]

// ---- f32x2 packed-FMA helpers (Blackwell) ----
__device__ __forceinline__ unsigned long long pack2(float lo, float hi) {
    unsigned long long r;
    asm("mov.b64 %0, {%1, %2};" : "=l"(r) : "f"(lo), "f"(hi));
    return r;
}
__device__ __forceinline__ void fma2(unsigned long long& acc, unsigned long long a,
                                     unsigned long long b) {
    asm("fma.rn.f32x2 %0, %1, %2, %0;" : "+l"(acc) : "l"(a), "l"(b));
}
__device__ __forceinline__ float unpack_sum(unsigned long long a) {
    float lo, hi;
    asm("mov.b64 {%0, %1}, %2;" : "=f"(lo), "=f"(hi) : "l"(a));
    return lo + hi;
}

// ---------------------------------------------------------------------------
__global__ void k_init() {
    int t = blockIdx.x * blockDim.x + threadIdx.x;
    if (t < CC * NU) {
        d_bij[t] = 0.0f;
        d_cij[t] = 0.1f;   // softmax(0) over 10 units
    }
}

// ---------------------------------------------------------------------------
// One block per capsule c, one thread per batch b.
__global__ void __launch_bounds__(BB) k_uhat(const float* __restrict__ x,
                                             const float* __restrict__ W) {
    const int c = blockIdx.x;
    const int b = threadIdx.x;

    __shared__ __align__(16) float Ws[WSZ];           // 20 KB
    const float* Wc = W + (size_t)c * WSZ;
    for (int t = b; t < WSZ; t += BB) Ws[t] = Wc[t];

    // x[b, i, c] — strided (L2-resident after first wave)
    float xr[IU];
    #pragma unroll
    for (int i = 0; i < IU; i++) xr[i] = __ldg(&x[(size_t)b * KX + i * CC + c]);

    unsigned long long xp[IU / 2];
    #pragma unroll
    for (int k = 0; k < IU / 2; k++) xp[k] = pack2(xr[2 * k], xr[2 * k + 1]);

    __syncthreads();

    __half* out = d_UH + (size_t)c * JJ * BB + b;
    #pragma unroll 1
    for (int j = 0; j < JJ; j += 2) {
        unsigned long long a0 = 0ull, a1 = 0ull;       // two f32x2 accumulators (=0.0f pair)
        const float4* w0 = (const float4*)&Ws[j * IU];
        const float4* w1 = (const float4*)&Ws[(j + 1) * IU];
        #pragma unroll
        for (int k = 0; k < 4; k++) {
            float4 wa = w0[k];
            float4 wb = w1[k];
            fma2(a0, pack2(wa.x, wa.y), xp[2 * k]);
            fma2(a0, pack2(wa.z, wa.w), xp[2 * k + 1]);
            fma2(a1, pack2(wb.x, wb.y), xp[2 * k]);
            fma2(a1, pack2(wb.z, wb.w), xp[2 * k + 1]);
        }
        out[(size_t)j * BB]       = __float2half(unpack_sum(a0));
        out[(size_t)(j + 1) * BB] = __float2half(unpack_sum(a1));
    }
}

// ---------------------------------------------------------------------------
// s-pass: grid (JJ, CSPLIT). Block (j, p) reduces c in [p*CCHUNK, (p+1)*CCHUNK).
__global__ void __launch_bounds__(BB) k_spass() {
    const int j = blockIdx.x;
    const int p = blockIdx.y;
    const int b = threadIdx.x;
    const int u = j >> 5;

    __shared__ float cs[CCHUNK];
    for (int t = b; t < CCHUNK; t += BB) cs[t] = d_cij[u * CC + p * CCHUNK + t];
    __syncthreads();

    const __half* uh = d_UH + (size_t)(p * CCHUNK) * JJ * BB + (size_t)j * BB + b;

    float acc[4] = {0.f, 0.f, 0.f, 0.f};
    #pragma unroll 1
    for (int c0 = 0; c0 < CCHUNK; c0 += 16) {
        #pragma unroll
        for (int k = 0; k < 16; k++) {
            float h = __half2float(__ldcs(uh + (size_t)(c0 + k) * JJ * BB));
            acc[k & 3] = fmaf(cs[c0 + k], h, acc[k & 3]);
        }
    }
    d_spart[p][j * BB + b] = (acc[0] + acc[1]) + (acc[2] + acc[3]);
}

// ---------------------------------------------------------------------------
// squash: grid (SS), thread = b. Reduction over u is in-block (same s).
// mag_sq reduces over the num_units axis (faithful to reference).
__global__ void __launch_bounds__(BB) k_squash(float* __restrict__ out) {
    const int s = blockIdx.x;
    const int b = threadIdx.x;

    float sv[NU];
    float q = 0.f;
    #pragma unroll
    for (int u = 0; u < NU; u++) {
        int idx = (u * SS + s) * BB + b;
        float v = d_spart[0][idx];
        #pragma unroll
        for (int p = 1; p < CSPLIT; p++) v += d_spart[p][idx];
        sv[u] = v;
        q = fmaf(v, v, q);
    }
    float mag = sqrtf(q);
    float f = q / ((1.0f + q) * mag);
    #pragma unroll
    for (int u = 0; u < NU; u++) {
        float v = sv[u] * f;
        d_vh[(u * SS + s) * BB + b] = __float2half(v);
        out[b * JJ + u * SS + s] = v;       // final iteration's write survives
    }
}

// ---------------------------------------------------------------------------
// agreement + b_ij update + softmax. One block per capsule c.
__global__ void __launch_bounds__(BB) k_apass() {
    const int c = blockIdx.x;
    const int b = threadIdx.x;
    const int lane = b & 31, wid = b >> 5;

    const __half* uh = d_UH + (size_t)c * JJ * BB + b;

    float au[NU];
    #pragma unroll
    for (int u = 0; u < NU; u++) au[u] = 0.f;

    #pragma unroll 1
    for (int u = 0; u < NU; u++) {
        float a = 0.f;
        #pragma unroll
        for (int s = 0; s < SS; s++) {
            int jb = (u * SS + s) * BB;
            float h = __half2float(__ldcs(uh + jb));          // streaming: don't evict v
            float v = __half2float(d_vh[jb + b]);             // L1-resident (160 KB)
            a = fmaf(h, v, a);
        }
        au[u] = a;
    }

    __shared__ float red[NU][8];
    #pragma unroll
    for (int u = 0; u < NU; u++) {
        float v = au[u];
        #pragma unroll
        for (int o = 16; o > 0; o >>= 1) v += __shfl_down_sync(0xffffffffu, v, o);
        if (lane == 0) red[u][wid] = v;
    }
    __syncthreads();

    __shared__ float bn[NU];
    if (b < NU) {
        float t = 0.f;
        #pragma unroll
        for (int w = 0; w < 8; w++) t += red[b][w];
        float v = d_bij[c * NU + b] + t * (1.0f / BB);
        d_bij[c * NU + b] = v;
        bn[b] = v;
    }
    __syncthreads();
    if (b < NU) {
        float m = bn[0];
        #pragma unroll
        for (int u = 1; u < NU; u++) m = fmaxf(m, bn[u]);
        float den = 0.f;
        #pragma unroll
        for (int u = 0; u < NU; u++) den += expf(bn[u] - m);
        d_cij[b * CC + c] = expf(bn[b] - m) / den;
    }
}

// ---------------------------------------------------------------------------
extern "C" void kernel_launch(void* const* d_in, const int* in_sizes, int n_in,
                              void* d_out, int out_size) {
    const float* x = (const float*)d_in[0];
    const float* W = (const float*)d_in[1];
    // defensive: identify by element count (x: 4718592, W: 5898240)
    if (n_in >= 2 && in_sizes[0] == CC * NU * SS * IU && in_sizes[1] == BB * IU * CC) {
        const float* t = x; x = W; W = t;
    }
    float* out = (float*)d_out;

    k_init<<<(CC * NU + 255) / 256, 256>>>();
    k_uhat<<<CC, BB>>>(x, W);

    dim3 sgrid(JJ, CSPLIT);
    // iteration 1
    k_spass<<<sgrid, BB>>>();
    k_squash<<<SS, BB>>>(out);
    k_apass<<<CC, BB>>>();
    // iteration 2
    k_spass<<<sgrid, BB>>>();
    k_squash<<<SS, BB>>>(out);
    k_apass<<<CC, BB>>>();
    // iteration 3 (b_ij update is discarded by the reference -> skip k_apass)
    k_spass<<<sgrid, BB>>>();
    k_squash<<<SS, BB>>>(out);
}